// round 7
// baseline (speedup 1.0000x reference)
#include <cuda_runtime.h>

#define NVOCAB 50001   // VOCAB + 1 rows
#define EMB    32
#define UNITS  16
#define BATCH  256
#define TLEN   4096
#define GATE3  48
#define PD     8       // prefetch depth (steps)

// Precomputed emb_table @ kernel + bias[0]  : [NVOCAB, 48]
__device__ float g_table2[NVOCAB * GATE3];

__device__ __forceinline__ float sigf(float x) {
    return __fdividef(1.0f, 1.0f + __expf(-x));
}

// ---------------------------------------------------------------------------
// Kernel A: g_table2[v][j] = sum_e emb[v][e] * kernel[e][j] + bias0[j]
// One warp per vocab row (strided). lane j -> col j; lanes 0-15 also col 32+j.
// ---------------------------------------------------------------------------
__global__ __launch_bounds__(128) void build_table(
    const float* __restrict__ emb,
    const float* __restrict__ kern,
    const float* __restrict__ bias)
{
    const int lane = threadIdx.x & 31;
    const int l2   = lane & 15;
    const int w    = (blockIdx.x * blockDim.x + threadIdx.x) >> 5;
    const int nw   = (gridDim.x * blockDim.x) >> 5;

    float KA[EMB], KB[EMB];
#pragma unroll
    for (int e = 0; e < EMB; e++) {
        KA[e] = kern[e * GATE3 + lane];
        KB[e] = kern[e * GATE3 + 32 + l2];
    }
    const float bA = bias[lane];
    const float bB = bias[32 + l2];

    for (int v = w; v < NVOCAB; v += nw) {
        float ev = emb[(long)v * EMB + lane];   // coalesced 128B
        float a = bA, b = bB;
#pragma unroll
        for (int e = 0; e < EMB; e++) {
            float s = __shfl_sync(0xffffffffu, ev, e);
            a = fmaf(s, KA[e], a);
            b = fmaf(s, KB[e], b);
        }
        g_table2[(long)v * GATE3 + lane] = a;
        if (lane < 16) g_table2[(long)v * GATE3 + 32 + lane] = b;
    }
}

// ---------------------------------------------------------------------------
// Kernel B: GRU scan. One batch per warp; 2 warps per CTA (one per SMSP 0/1).
// Column mapping per lane l:
//   c1 = l ^ 16  -> lanes 0-15 compute the r-column, lanes 16-31 the z-column
//   lanes 0-15 also own column 32+l (rh / candidate column)
// so both sigmoids of gate set #1 happen in one warp-wide pass and the z value
// is shuffled down while the candidate sigmoid is in flight.
// ---------------------------------------------------------------------------
__global__ __launch_bounds__(64, 1) void gru_scan(
    const int*   __restrict__ ids,
    const float* __restrict__ reck,
    const float* __restrict__ bias,
    float*       __restrict__ out)
{
    __shared__ int sid[2][TLEN];           // 32 KB: this warp's token ids

    const int lane = threadIdx.x & 31;
    const int w    = threadIdx.x >> 5;
    const int b    = blockIdx.x * 2 + w;

    // stage ids into smem (coalesced)
    const int* idp = ids + (long)b * TLEN;
    for (int k = lane; k < TLEN; k += 32) sid[w][k] = idp[k];
    __syncwarp();
    const int* sw = sid[w];

    const int c1 = lane ^ 16;
    const int l2 = lane & 15;

    // recurrent kernel columns in registers
    float R1[UNITS], R2[UNITS];
#pragma unroll
    for (int i = 0; i < UNITS; i++) {
        R1[i] = reck[i * GATE3 + c1];
        R2[i] = reck[i * GATE3 + 32 + l2];
    }
    const float b1 = bias[GATE3 + c1];        // recurrent bias, col c1
    const float b2 = bias[GATE3 + 32 + l2];   // recurrent bias, rh col

    float hv[UNITS];
#pragma unroll
    for (int i = 0; i < UNITS; i++) hv[i] = 0.0f;
    float hcur = 0.0f;                         // lane u (<16) holds h[u]

    // prefetch ring for input-projection rows (x1 = col c1, x2 = col 32+l2)
    float x1b[PD], x2b[PD];
#pragma unroll
    for (int k = 0; k < PD; k++) {
        const float* row = g_table2 + (long)sw[k] * GATE3;
        x1b[k] = row[c1];
        x2b[k] = row[32 + l2];
    }

    for (int t0 = 0; t0 < TLEN; t0 += PD) {
#pragma unroll
        for (int k = 0; k < PD; k++) {
            const float x1 = x1b[k];
            const float x2 = x2b[k];

            // refill ring PD steps ahead (off the critical path)
            int tn  = t0 + k + PD;
            int idn = sw[(tn < TLEN) ? tn : 0];
            const float* row = g_table2 + (long)idn * GATE3;
            x1b[k] = row[c1];
            x2b[k] = row[32 + l2];

            // rec matvec, 4-way split chains (fold bias + x1 into chain 0)
            const float bx = b1 + x1;
            float p0 = fmaf(hv[0],  R1[0],  fmaf(hv[4],  R1[4],
                       fmaf(hv[8],  R1[8],  fmaf(hv[12], R1[12], bx))));
            float p1 = fmaf(hv[1],  R1[1],  fmaf(hv[5],  R1[5],
                       fmaf(hv[9],  R1[9],  hv[13] * R1[13])));
            float p2 = fmaf(hv[2],  R1[2],  fmaf(hv[6],  R1[6],
                       fmaf(hv[10], R1[10], hv[14] * R1[14])));
            float p3 = fmaf(hv[3],  R1[3],  fmaf(hv[7],  R1[7],
                       fmaf(hv[11], R1[11], hv[15] * R1[15])));
            float acc1 = (p0 + p1) + (p2 + p3);   // = x1 + (h@R + b)[c1]

            float q0 = fmaf(hv[0],  R2[0],  fmaf(hv[4],  R2[4],
                       fmaf(hv[8],  R2[8],  fmaf(hv[12], R2[12], b2))));
            float q1 = fmaf(hv[1],  R2[1],  fmaf(hv[5],  R2[5],
                       fmaf(hv[9],  R2[9],  hv[13] * R2[13])));
            float q2 = fmaf(hv[2],  R2[2],  fmaf(hv[6],  R2[6],
                       fmaf(hv[10], R2[10], hv[14] * R2[14])));
            float q3 = fmaf(hv[3],  R2[3],  fmaf(hv[7],  R2[7],
                       fmaf(hv[11], R2[11], hv[15] * R2[15])));
            float acc2 = (q0 + q1) + (q2 + q3);   // = (h@R + b)[32+l2]

            // gate set 1: lanes<16 -> r, lanes>=16 -> z (same instructions)
            float g1 = sigf(acc1);
            // pull z_u down from lane u+16; overlaps the candidate sigmoid
            float z  = __shfl_down_sync(0xffffffffu, g1, 16);
            // candidate: hh = sigmoid(xh + r * rh)   (lanes<16 meaningful)
            float hh = sigf(fmaf(g1, acc2, x2));
            // h_new = z*h + (1-z)*hh
            float hn = fmaf(z, hcur - hh, hh);
            hcur = hn;

            // broadcast new state to all lanes
#pragma unroll
            for (int i = 0; i < UNITS; i++)
                hv[i] = __shfl_sync(0xffffffffu, hn, i);
        }
    }

    if (lane < 16) out[(long)b * UNITS + lane] = hcur;
}

// ---------------------------------------------------------------------------
extern "C" void kernel_launch(void* const* d_in, const int* in_sizes, int n_in,
                              void* d_out, int out_size)
{
    const int*   ids  = (const int*)  d_in[0];   // [256, 4096] int32
    const float* emb  = (const float*)d_in[1];   // [50001, 32]
    const float* kern = (const float*)d_in[2];   // [32, 48]
    const float* reck = (const float*)d_in[3];   // [16, 48]
    const float* bias = (const float*)d_in[4];   // [2, 48]
    float*       out  = (float*)d_out;           // [256, 16]

    (void)in_sizes; (void)n_in; (void)out_size;

    build_table<<<256, 128>>>(emb, kern, bias);
    gru_scan<<<BATCH / 2, 64>>>(ids, reck, bias, out);
}

// round 8
// speedup vs baseline: 1.0002x; 1.0002x over previous
#include <cuda_runtime.h>

#define NVOCAB 50001   // VOCAB + 1 rows
#define EMB    32
#define UNITS  16
#define BATCH  256
#define TLEN   4096
#define GATE3  48
#define PD     8       // prefetch depth (steps)

// Precomputed emb_table @ kernel + bias[0]  : [NVOCAB, 48]
__device__ float g_table2[NVOCAB * GATE3];

__device__ __forceinline__ float sigf(float x) {
    return __fdividef(1.0f, 1.0f + __expf(-x));
}

// ---------------------------------------------------------------------------
// Kernel A: g_table2[v][j] = sum_e emb[v][e] * kernel[e][j] + bias0[j]
// One warp per vocab row (strided). lane j -> col j; lanes 0-15 also col 32+j.
// ---------------------------------------------------------------------------
__global__ __launch_bounds__(128) void build_table(
    const float* __restrict__ emb,
    const float* __restrict__ kern,
    const float* __restrict__ bias)
{
    const int lane = threadIdx.x & 31;
    const int l2   = lane & 15;
    const int w    = (blockIdx.x * blockDim.x + threadIdx.x) >> 5;
    const int nw   = (gridDim.x * blockDim.x) >> 5;

    float KA[EMB], KB[EMB];
#pragma unroll
    for (int e = 0; e < EMB; e++) {
        KA[e] = kern[e * GATE3 + lane];
        KB[e] = kern[e * GATE3 + 32 + l2];
    }
    const float bA = bias[lane];
    const float bB = bias[32 + l2];

    for (int v = w; v < NVOCAB; v += nw) {
        float ev = emb[(long)v * EMB + lane];   // coalesced 128B
        float a = bA, b = bB;
#pragma unroll
        for (int e = 0; e < EMB; e++) {
            float s = __shfl_sync(0xffffffffu, ev, e);
            a = fmaf(s, KA[e], a);
            b = fmaf(s, KB[e], b);
        }
        g_table2[(long)v * GATE3 + lane] = a;
        if (lane < 16) g_table2[(long)v * GATE3 + 32 + lane] = b;
    }
}

// ---------------------------------------------------------------------------
// Kernel B: GRU scan. One batch per warp; 2 warps per CTA (one per SMSP 0/1).
// Column mapping per lane l:
//   c1 = l ^ 16  -> lanes 0-15 compute the r-column, lanes 16-31 the z-column
//   lanes 0-15 also own column 32+l (rh / candidate column)
// so both sigmoids of gate set #1 happen in one warp-wide pass and the z value
// is shuffled down while the candidate sigmoid is in flight.
// ---------------------------------------------------------------------------
__global__ __launch_bounds__(64, 1) void gru_scan(
    const int*   __restrict__ ids,
    const float* __restrict__ reck,
    const float* __restrict__ bias,
    float*       __restrict__ out)
{
    __shared__ int sid[2][TLEN];           // 32 KB: this warp's token ids

    const int lane = threadIdx.x & 31;
    const int w    = threadIdx.x >> 5;
    const int b    = blockIdx.x * 2 + w;

    // stage ids into smem (coalesced)
    const int* idp = ids + (long)b * TLEN;
    for (int k = lane; k < TLEN; k += 32) sid[w][k] = idp[k];
    __syncwarp();
    const int* sw = sid[w];

    const int c1 = lane ^ 16;
    const int l2 = lane & 15;

    // recurrent kernel columns in registers
    float R1[UNITS], R2[UNITS];
#pragma unroll
    for (int i = 0; i < UNITS; i++) {
        R1[i] = reck[i * GATE3 + c1];
        R2[i] = reck[i * GATE3 + 32 + l2];
    }
    const float b1 = bias[GATE3 + c1];        // recurrent bias, col c1
    const float b2 = bias[GATE3 + 32 + l2];   // recurrent bias, rh col

    float hv[UNITS];
#pragma unroll
    for (int i = 0; i < UNITS; i++) hv[i] = 0.0f;
    float hcur = 0.0f;                         // lane u (<16) holds h[u]

    // prefetch ring for input-projection rows (x1 = col c1, x2 = col 32+l2)
    float x1b[PD], x2b[PD];
#pragma unroll
    for (int k = 0; k < PD; k++) {
        const float* row = g_table2 + (long)sw[k] * GATE3;
        x1b[k] = row[c1];
        x2b[k] = row[32 + l2];
    }

    for (int t0 = 0; t0 < TLEN; t0 += PD) {
#pragma unroll
        for (int k = 0; k < PD; k++) {
            const float x1 = x1b[k];
            const float x2 = x2b[k];

            // refill ring PD steps ahead (off the critical path)
            int tn  = t0 + k + PD;
            int idn = sw[(tn < TLEN) ? tn : 0];
            const float* row = g_table2 + (long)idn * GATE3;
            x1b[k] = row[c1];
            x2b[k] = row[32 + l2];

            // rec matvec, 4-way split chains (fold bias + x1 into chain 0)
            const float bx = b1 + x1;
            float p0 = fmaf(hv[0],  R1[0],  fmaf(hv[4],  R1[4],
                       fmaf(hv[8],  R1[8],  fmaf(hv[12], R1[12], bx))));
            float p1 = fmaf(hv[1],  R1[1],  fmaf(hv[5],  R1[5],
                       fmaf(hv[9],  R1[9],  hv[13] * R1[13])));
            float p2 = fmaf(hv[2],  R1[2],  fmaf(hv[6],  R1[6],
                       fmaf(hv[10], R1[10], hv[14] * R1[14])));
            float p3 = fmaf(hv[3],  R1[3],  fmaf(hv[7],  R1[7],
                       fmaf(hv[11], R1[11], hv[15] * R1[15])));
            float acc1 = (p0 + p1) + (p2 + p3);   // = x1 + (h@R + b)[c1]

            float q0 = fmaf(hv[0],  R2[0],  fmaf(hv[4],  R2[4],
                       fmaf(hv[8],  R2[8],  fmaf(hv[12], R2[12], b2))));
            float q1 = fmaf(hv[1],  R2[1],  fmaf(hv[5],  R2[5],
                       fmaf(hv[9],  R2[9],  hv[13] * R2[13])));
            float q2 = fmaf(hv[2],  R2[2],  fmaf(hv[6],  R2[6],
                       fmaf(hv[10], R2[10], hv[14] * R2[14])));
            float q3 = fmaf(hv[3],  R2[3],  fmaf(hv[7],  R2[7],
                       fmaf(hv[11], R2[11], hv[15] * R2[15])));
            float acc2 = (q0 + q1) + (q2 + q3);   // = (h@R + b)[32+l2]

            // gate set 1: lanes<16 -> r, lanes>=16 -> z (same instructions)
            float g1 = sigf(acc1);
            // pull z_u down from lane u+16; overlaps the candidate sigmoid
            float z  = __shfl_down_sync(0xffffffffu, g1, 16);
            // candidate: hh = sigmoid(xh + r * rh)   (lanes<16 meaningful)
            float hh = sigf(fmaf(g1, acc2, x2));
            // h_new = z*h + (1-z)*hh
            float hn = fmaf(z, hcur - hh, hh);
            hcur = hn;

            // broadcast new state to all lanes
#pragma unroll
            for (int i = 0; i < UNITS; i++)
                hv[i] = __shfl_sync(0xffffffffu, hn, i);
        }
    }

    if (lane < 16) out[(long)b * UNITS + lane] = hcur;
}

// ---------------------------------------------------------------------------
extern "C" void kernel_launch(void* const* d_in, const int* in_sizes, int n_in,
                              void* d_out, int out_size)
{
    const int*   ids  = (const int*)  d_in[0];   // [256, 4096] int32
    const float* emb  = (const float*)d_in[1];   // [50001, 32]
    const float* kern = (const float*)d_in[2];   // [32, 48]
    const float* reck = (const float*)d_in[3];   // [16, 48]
    const float* bias = (const float*)d_in[4];   // [2, 48]
    float*       out  = (float*)d_out;           // [256, 16]

    (void)in_sizes; (void)n_in; (void)out_size;

    build_table<<<256, 128>>>(emb, kern, bias);
    gru_scan<<<BATCH / 2, 64>>>(ids, reck, bias, out);
}

// round 9
// speedup vs baseline: 1.0012x; 1.0010x over previous
#include <cuda_runtime.h>

#define NVOCAB 50001   // VOCAB + 1 rows
#define EMB    32
#define UNITS  16
#define BATCH  256
#define TLEN   4096
#define GATE3  48
#define PD     8       // prefetch depth (steps)

// Precomputed emb_table @ kernel + bias[0]  : [NVOCAB, 48]
__device__ float g_table2[NVOCAB * GATE3];

__device__ __forceinline__ float sigf(float x) {
    return __fdividef(1.0f, 1.0f + __expf(-x));
}

// ---------------------------------------------------------------------------
// Kernel A: g_table2[v][j] = sum_e emb[v][e] * kernel[e][j] + bias0[j]
// One warp per vocab row (strided). lane j -> col j; lanes 0-15 also col 32+j.
// ---------------------------------------------------------------------------
__global__ __launch_bounds__(128) void build_table(
    const float* __restrict__ emb,
    const float* __restrict__ kern,
    const float* __restrict__ bias)
{
    const int lane = threadIdx.x & 31;
    const int l2   = lane & 15;
    const int w    = (blockIdx.x * blockDim.x + threadIdx.x) >> 5;
    const int nw   = (gridDim.x * blockDim.x) >> 5;

    float KA[EMB], KB[EMB];
#pragma unroll
    for (int e = 0; e < EMB; e++) {
        KA[e] = kern[e * GATE3 + lane];
        KB[e] = kern[e * GATE3 + 32 + l2];
    }
    const float bA = bias[lane];
    const float bB = bias[32 + l2];

    for (int v = w; v < NVOCAB; v += nw) {
        float ev = emb[(long)v * EMB + lane];   // coalesced 128B
        float a = bA, b = bB;
#pragma unroll
        for (int e = 0; e < EMB; e++) {
            float s = __shfl_sync(0xffffffffu, ev, e);
            a = fmaf(s, KA[e], a);
            b = fmaf(s, KB[e], b);
        }
        g_table2[(long)v * GATE3 + lane] = a;
        if (lane < 16) g_table2[(long)v * GATE3 + 32 + lane] = b;
    }
}

// ---------------------------------------------------------------------------
// Kernel B: GRU scan. One batch per warp; 2 warps per CTA (one per SMSP 0/1).
// Column mapping per lane l:
//   c1 = l ^ 16  -> lanes 0-15 compute the r-column, lanes 16-31 the z-column
//   lanes 0-15 also own column 32+l (rh / candidate column)
// so both sigmoids of gate set #1 happen in one warp-wide pass and the z value
// is shuffled down while the candidate sigmoid is in flight.
// ---------------------------------------------------------------------------
__global__ __launch_bounds__(64, 1) void gru_scan(
    const int*   __restrict__ ids,
    const float* __restrict__ reck,
    const float* __restrict__ bias,
    float*       __restrict__ out)
{
    __shared__ int sid[2][TLEN];           // 32 KB: this warp's token ids

    const int lane = threadIdx.x & 31;
    const int w    = threadIdx.x >> 5;
    const int b    = blockIdx.x * 2 + w;

    // stage ids into smem (coalesced)
    const int* idp = ids + (long)b * TLEN;
    for (int k = lane; k < TLEN; k += 32) sid[w][k] = idp[k];
    __syncwarp();
    const int* sw = sid[w];

    const int c1 = lane ^ 16;
    const int l2 = lane & 15;

    // recurrent kernel columns in registers
    float R1[UNITS], R2[UNITS];
#pragma unroll
    for (int i = 0; i < UNITS; i++) {
        R1[i] = reck[i * GATE3 + c1];
        R2[i] = reck[i * GATE3 + 32 + l2];
    }
    const float b1 = bias[GATE3 + c1];        // recurrent bias, col c1
    const float b2 = bias[GATE3 + 32 + l2];   // recurrent bias, rh col

    float hv[UNITS];
#pragma unroll
    for (int i = 0; i < UNITS; i++) hv[i] = 0.0f;
    float hcur = 0.0f;                         // lane u (<16) holds h[u]

    // prefetch ring for input-projection rows (x1 = col c1, x2 = col 32+l2)
    float x1b[PD], x2b[PD];
#pragma unroll
    for (int k = 0; k < PD; k++) {
        const float* row = g_table2 + (long)sw[k] * GATE3;
        x1b[k] = row[c1];
        x2b[k] = row[32 + l2];
    }

    for (int t0 = 0; t0 < TLEN; t0 += PD) {
#pragma unroll
        for (int k = 0; k < PD; k++) {
            const float x1 = x1b[k];
            const float x2 = x2b[k];

            // refill ring PD steps ahead (off the critical path)
            int tn  = t0 + k + PD;
            int idn = sw[(tn < TLEN) ? tn : 0];
            const float* row = g_table2 + (long)idn * GATE3;
            x1b[k] = row[c1];
            x2b[k] = row[32 + l2];

            // rec matvec, 4-way split chains (fold bias + x1 into chain 0)
            const float bx = b1 + x1;
            float p0 = fmaf(hv[0],  R1[0],  fmaf(hv[4],  R1[4],
                       fmaf(hv[8],  R1[8],  fmaf(hv[12], R1[12], bx))));
            float p1 = fmaf(hv[1],  R1[1],  fmaf(hv[5],  R1[5],
                       fmaf(hv[9],  R1[9],  hv[13] * R1[13])));
            float p2 = fmaf(hv[2],  R1[2],  fmaf(hv[6],  R1[6],
                       fmaf(hv[10], R1[10], hv[14] * R1[14])));
            float p3 = fmaf(hv[3],  R1[3],  fmaf(hv[7],  R1[7],
                       fmaf(hv[11], R1[11], hv[15] * R1[15])));
            float acc1 = (p0 + p1) + (p2 + p3);   // = x1 + (h@R + b)[c1]

            float q0 = fmaf(hv[0],  R2[0],  fmaf(hv[4],  R2[4],
                       fmaf(hv[8],  R2[8],  fmaf(hv[12], R2[12], b2))));
            float q1 = fmaf(hv[1],  R2[1],  fmaf(hv[5],  R2[5],
                       fmaf(hv[9],  R2[9],  hv[13] * R2[13])));
            float q2 = fmaf(hv[2],  R2[2],  fmaf(hv[6],  R2[6],
                       fmaf(hv[10], R2[10], hv[14] * R2[14])));
            float q3 = fmaf(hv[3],  R2[3],  fmaf(hv[7],  R2[7],
                       fmaf(hv[11], R2[11], hv[15] * R2[15])));
            float acc2 = (q0 + q1) + (q2 + q3);   // = (h@R + b)[32+l2]

            // gate set 1: lanes<16 -> r, lanes>=16 -> z (same instructions)
            float g1 = sigf(acc1);
            // pull z_u down from lane u+16; overlaps the candidate sigmoid
            float z  = __shfl_down_sync(0xffffffffu, g1, 16);
            // candidate: hh = sigmoid(xh + r * rh)   (lanes<16 meaningful)
            float hh = sigf(fmaf(g1, acc2, x2));
            // h_new = z*h + (1-z)*hh
            float hn = fmaf(z, hcur - hh, hh);
            hcur = hn;

            // broadcast new state to all lanes
#pragma unroll
            for (int i = 0; i < UNITS; i++)
                hv[i] = __shfl_sync(0xffffffffu, hn, i);
        }
    }

    if (lane < 16) out[(long)b * UNITS + lane] = hcur;
}

// ---------------------------------------------------------------------------
extern "C" void kernel_launch(void* const* d_in, const int* in_sizes, int n_in,
                              void* d_out, int out_size)
{
    const int*   ids  = (const int*)  d_in[0];   // [256, 4096] int32
    const float* emb  = (const float*)d_in[1];   // [50001, 32]
    const float* kern = (const float*)d_in[2];   // [32, 48]
    const float* reck = (const float*)d_in[3];   // [16, 48]
    const float* bias = (const float*)d_in[4];   // [2, 48]
    float*       out  = (float*)d_out;           // [256, 16]

    (void)in_sizes; (void)n_in; (void)out_size;

    build_table<<<256, 128>>>(emb, kern, bias);
    gru_scan<<<BATCH / 2, 64>>>(ids, reck, bias, out);
}